// round 2
// baseline (speedup 1.0000x reference)
#include <cuda_runtime.h>

#define Bsz 8
#define Pt 12
#define Nn 5000
#define Dm 64
#define NPB 16
#define THREADS 256
#define RM_STRIDE 776      // row-major node buffer stride (12*64 + 8)
#define XT_ROW 14          // transposed buffer row stride (12 + 2 pad, even for LDS.64)
#define XT_NODE 902        // 64*14 + 6 ; mod 32 = 6 -> groups hit disjoint banks
#define WT_STRIDE 66
#define NND (Nn * Dm)

typedef unsigned long long u64;

__device__ __forceinline__ u64 fma2(u64 a, u64 b, u64 c) {
    u64 d;
    asm("fma.rn.f32x2 %0, %1, %2, %3;" : "=l"(d) : "l"(a), "l"(b), "l"(c));
    return d;
}
__device__ __forceinline__ u64 mul2(u64 a, u64 b) {
    u64 d;
    asm("mul.rn.f32x2 %0, %1, %2;" : "=l"(d) : "l"(a), "l"(b));
    return d;
}
__device__ __forceinline__ u64 dup2(float x) {
    u64 d; unsigned r = __float_as_uint(x);
    asm("mov.b64 %0, {%1, %1};" : "=l"(d) : "r"(r));
    return d;
}
__device__ __forceinline__ float2 unpack2(u64 v) {
    unsigned lo, hi;
    asm("mov.b64 {%0, %1}, %2;" : "=r"(lo), "=r"(hi) : "l"(v));
    return make_float2(__uint_as_float(lo), __uint_as_float(hi));
}

// Stage one 64x64 weight into smem TRANSPOSED (sWt[i*66 + j] = W[j*64 + i]).
__device__ __forceinline__ void load_weight(const float* __restrict__ Wg,
                                            const float* __restrict__ bg,
                                            float* __restrict__ sWt,
                                            float* __restrict__ sBias,
                                            int tid)
{
#pragma unroll
    for (int r = 0; r < 16; r++) {
        int idx = r * 256 + tid;
        int j = idx >> 6;
        int i = idx & 63;
        sWt[i * WT_STRIDE + j] = Wg[idx];
    }
    if (tid < 64) sBias[tid] = bg[tid];
}

// Stage a 12x64 input slab TRANSPOSED: xT[i*14 + t] = src[t*NND + i]
// (thread l owns columns i = 4l..4l+3; global reads are float4-coalesced)
__device__ __forceinline__ void stage_input_T(const float* __restrict__ src,
                                              float* __restrict__ xT, int l)
{
    float4 r[12];
#pragma unroll
    for (int t = 0; t < 12; t++)
        r[t] = *(const float4*)(src + t * NND + l * 4);
#pragma unroll
    for (int c = 0; c < 4; c++) {
        float* col = xT + (l * 4 + c) * XT_ROW;
#pragma unroll
        for (int t = 0; t < 12; t++)
            col[t] = ((const float*)&r[t])[c];
    }
}

// 12x64 GEMM accumulate. Row-pair packed accumulators:
// acc[m][c] = (out[2m][j0+c], out[2m+1][j0+c]).
// Weight dup hoisted: 4 dups per i reused over 6 row-pairs (24 FFMA2).
__device__ __forceinline__ void gemm_acc(const float* __restrict__ xT,
                                         const float* __restrict__ sWt,
                                         const float* __restrict__ sBias,
                                         int j0, u64 acc[6][4])
{
    const u64 b0 = dup2(sBias[j0 + 0]);
    const u64 b1 = dup2(sBias[j0 + 1]);
    const u64 b2 = dup2(sBias[j0 + 2]);
    const u64 b3 = dup2(sBias[j0 + 3]);
#pragma unroll
    for (int m = 0; m < 6; m++) {
        acc[m][0] = b0; acc[m][1] = b1; acc[m][2] = b2; acc[m][3] = b3;
    }

#pragma unroll 8
    for (int i = 0; i < 64; i++) {
        const float* w = sWt + i * WT_STRIDE + j0;
        const float2 wab = *(const float2*)w;
        const float2 wcd = *(const float2*)(w + 2);
        const u64 wd0 = dup2(wab.x);
        const u64 wd1 = dup2(wab.y);
        const u64 wd2 = dup2(wcd.x);
        const u64 wd3 = dup2(wcd.y);
        const float* xr = xT + i * XT_ROW;
#pragma unroll
        for (int m = 0; m < 6; m++) {
            const u64 xp = *(const u64*)(xr + 2 * m);   // (x[2m][i], x[2m+1][i]) broadcast
            acc[m][0] = fma2(xp, wd0, acc[m][0]);
            acc[m][1] = fma2(xp, wd1, acc[m][1]);
            acc[m][2] = fma2(xp, wd2, acc[m][2]);
            acc[m][3] = fma2(xp, wd3, acc[m][3]);
        }
    }
}

// Epilogue: row-major store (smem node buffer or global), optional relu.
__device__ __forceinline__ void epi_rows(const u64 acc[6][4], float* __restrict__ dst,
                                         int dstride, int j0, bool relu)
{
#pragma unroll
    for (int m = 0; m < 6; m++) {
        float2 a0 = unpack2(acc[m][0]);
        float2 a1 = unpack2(acc[m][1]);
        float2 a2 = unpack2(acc[m][2]);
        float2 a3 = unpack2(acc[m][3]);
        float4 r0 = make_float4(a0.x, a1.x, a2.x, a3.x);
        float4 r1 = make_float4(a0.y, a1.y, a2.y, a3.y);
        if (relu) {
            r0.x = fmaxf(r0.x, 0.f); r0.y = fmaxf(r0.y, 0.f);
            r0.z = fmaxf(r0.z, 0.f); r0.w = fmaxf(r0.w, 0.f);
            r1.x = fmaxf(r1.x, 0.f); r1.y = fmaxf(r1.y, 0.f);
            r1.z = fmaxf(r1.z, 0.f); r1.w = fmaxf(r1.w, 0.f);
        }
        *(float4*)(dst + (2 * m) * dstride + j0)     = r0;
        *(float4*)(dst + (2 * m + 1) * dstride + j0) = r1;
    }
}

// Epilogue: transposed store into xT with relu (acc pairs are (t,t+1): direct STS.64).
__device__ __forceinline__ void epi_transT_relu(const u64 acc[6][4],
                                                float* __restrict__ xT, int j0)
{
#pragma unroll
    for (int c = 0; c < 4; c++) {
        float* col = xT + (j0 + c) * XT_ROW;
#pragma unroll
        for (int m = 0; m < 6; m++) {
            float2 a = unpack2(acc[m][c]);
            a.x = fmaxf(a.x, 0.f);
            a.y = fmaxf(a.y, 0.f);
            *(float2*)(col + 2 * m) = a;
        }
    }
}

// Per-node attention (8 heads, 12 q, 12 p, d=8), f32x2-packed.
// Thread: head = l&7, q-range = (l>>3)*6 .. +5, processed as 3 q-pairs
// (shares the k/v loads between the two q's). Output written TRANSPOSED to xT.
__device__ __forceinline__ void attention(const float* __restrict__ myQ,
                                          const float* __restrict__ myK,
                                          const float* __restrict__ myV,
                                          float* __restrict__ xT, int l)
{
    const int h8 = (l & 7) * 8;
    const int qbase = (l >> 3) * 6;
    const float scale = 0.35355339059327373f;   // 1/sqrt(8)
#pragma unroll
    for (int mm = 0; mm < 3; mm++) {
        const int qa = qbase + 2 * mm;
        u64 qpA[4], qpB[4];
#pragma unroll
        for (int e = 0; e < 4; e++) {
            qpA[e] = *(const u64*)(myQ + qa * 64 + h8 + 2 * e);
            qpB[e] = *(const u64*)(myQ + (qa + 1) * 64 + h8 + 2 * e);
        }
        float sA[12], sB[12];
        float mxA = -1e30f, mxB = -1e30f;
#pragma unroll
        for (int p = 0; p < 12; p++) {
            const u64 kp0 = *(const u64*)(myK + p * 64 + h8 + 0);
            const u64 kp1 = *(const u64*)(myK + p * 64 + h8 + 2);
            const u64 kp2 = *(const u64*)(myK + p * 64 + h8 + 4);
            const u64 kp3 = *(const u64*)(myK + p * 64 + h8 + 6);
            u64 dA = fma2(qpA[0], kp0, fma2(qpA[1], kp1, fma2(qpA[2], kp2, mul2(qpA[3], kp3))));
            u64 dB = fma2(qpB[0], kp0, fma2(qpB[1], kp1, fma2(qpB[2], kp2, mul2(qpB[3], kp3))));
            float2 tA = unpack2(dA), tB = unpack2(dB);
            sA[p] = (tA.x + tA.y) * scale;
            sB[p] = (tB.x + tB.y) * scale;
            mxA = fmaxf(mxA, sA[p]);
            mxB = fmaxf(mxB, sB[p]);
        }
        float sumA = 0.f, sumB = 0.f;
#pragma unroll
        for (int p = 0; p < 12; p++) {
            sA[p] = __expf(sA[p] - mxA); sumA += sA[p];
            sB[p] = __expf(sB[p] - mxB); sumB += sB[p];
        }
        const float invA = __fdividef(1.f, sumA);
        const float invB = __fdividef(1.f, sumB);

        u64 oA[4], oB[4];
        const u64 z = dup2(0.f);
#pragma unroll
        for (int e = 0; e < 4; e++) { oA[e] = z; oB[e] = z; }
#pragma unroll
        for (int p = 0; p < 12; p++) {
            const u64 aA = dup2(sA[p] * invA);
            const u64 aB = dup2(sB[p] * invB);
#pragma unroll
            for (int e = 0; e < 4; e++) {
                const u64 vp = *(const u64*)(myV + p * 64 + h8 + 2 * e);
                oA[e] = fma2(vp, aA, oA[e]);
                oB[e] = fma2(vp, aB, oB[e]);
            }
        }
#pragma unroll
        for (int e = 0; e < 4; e++) {
            float2 a = unpack2(oA[e]);
            float2 b = unpack2(oB[e]);
            xT[(h8 + 2 * e)     * XT_ROW + qa]     = a.x;
            xT[(h8 + 2 * e + 1) * XT_ROW + qa]     = a.y;
            xT[(h8 + 2 * e)     * XT_ROW + qa + 1] = b.x;
            xT[(h8 + 2 * e + 1) * XT_ROW + qa + 1] = b.y;
        }
    }
}

__global__ void __launch_bounds__(THREADS)
fused_attn_kernel(const float* __restrict__ X,
                  const float* __restrict__ STE_P,
                  const float* __restrict__ STE_Q,
                  const float* __restrict__ W21, const float* __restrict__ b21,
                  const float* __restrict__ W22, const float* __restrict__ b22,
                  const float* __restrict__ W23, const float* __restrict__ b23,
                  const float* __restrict__ W24, const float* __restrict__ b24,
                  const float* __restrict__ W25, const float* __restrict__ b25,
                  float* __restrict__ Out)
{
    extern __shared__ float smem[];
    float* sWt   = smem;                         // 64*66 = 4224
    float* sBias = sWt + 64 * WT_STRIDE;         // 64
    float* sXT   = sBias + 64;                   // 16 * 902 (transposed staging)
    float* sQ    = sXT + NPB * XT_NODE;          // 16 * 776
    float* sK    = sQ  + NPB * RM_STRIDE;
    float* sV    = sK  + NPB * RM_STRIDE;

    const int tid = threadIdx.x;
    const int g   = tid >> 4;
    const int l   = tid & 15;
    const int j0  = l * 4;
    const int b   = blockIdx.y;
    const int n   = blockIdx.x * NPB + g;
    const bool valid = (n < Nn);

    float* myXT = sXT + g * XT_NODE;
    float* myQ  = sQ  + g * RM_STRIDE;
    float* myK  = sK  + g * RM_STRIDE;
    float* myV  = sV  + g * RM_STRIDE;

    const int gbase = b * (Pt * NND) + n * Dm;

    u64 acc[6][4];

    // ---- Phase A: q = relu(STE_Q @ W21^T + b21) ----
    load_weight(W21, b21, sWt, sBias, tid);
    if (valid) stage_input_T(STE_Q + gbase, myXT, l);
    __syncthreads();
    if (valid) { gemm_acc(myXT, sWt, sBias, j0, acc); epi_rows(acc, myQ, 64, j0, true); }
    __syncthreads();

    // ---- Phase B: k = relu(STE_P @ W22^T + b22) ----
    load_weight(W22, b22, sWt, sBias, tid);
    if (valid) stage_input_T(STE_P + gbase, myXT, l);
    __syncthreads();
    if (valid) { gemm_acc(myXT, sWt, sBias, j0, acc); epi_rows(acc, myK, 64, j0, true); }
    __syncthreads();

    // ---- Phase C: v = relu(X @ W23^T + b23) ----
    load_weight(W23, b23, sWt, sBias, tid);
    if (valid) stage_input_T(X + gbase, myXT, l);
    __syncthreads();
    if (valid) { gemm_acc(myXT, sWt, sBias, j0, acc); epi_rows(acc, myV, 64, j0, true); }
    __syncthreads();

    // ---- Attention: writes transposed result into myXT ----
    if (valid) attention(myQ, myK, myV, myXT, l);
    __syncthreads();

    // ---- Phase D: h = relu(attn @ W24^T + b24), written transposed in-place ----
    load_weight(W24, b24, sWt, sBias, tid);
    __syncthreads();
    if (valid) gemm_acc(myXT, sWt, sBias, j0, acc);
    __syncthreads();                 // all reads of myXT done before in-place write
    if (valid) epi_transT_relu(acc, myXT, j0);
    __syncthreads();

    // ---- Phase E: out = h @ W25^T + b25 -> global ----
    load_weight(W25, b25, sWt, sBias, tid);
    __syncthreads();
    if (valid) {
        gemm_acc(myXT, sWt, sBias, j0, acc);
        epi_rows(acc, Out + gbase, NND, j0, false);
    }
}

extern "C" void kernel_launch(void* const* d_in, const int* in_sizes, int n_in,
                              void* d_out, int out_size)
{
    const float* X     = (const float*)d_in[0];
    const float* STE_P = (const float*)d_in[1];
    const float* STE_Q = (const float*)d_in[2];
    const float* W21   = (const float*)d_in[3];
    const float* b21   = (const float*)d_in[4];
    const float* W22   = (const float*)d_in[5];
    const float* b22   = (const float*)d_in[6];
    const float* W23   = (const float*)d_in[7];
    const float* b23   = (const float*)d_in[8];
    const float* W24   = (const float*)d_in[9];
    const float* b24   = (const float*)d_in[10];
    const float* W25   = (const float*)d_in[11];
    const float* b25   = (const float*)d_in[12];
    float* Out = (float*)d_out;

    const size_t smem_bytes =
        (size_t)(64 * WT_STRIDE + 64 + NPB * XT_NODE + 3 * NPB * RM_STRIDE)
        * sizeof(float);   // 223,872 B

    cudaFuncSetAttribute(fused_attn_kernel,
                         cudaFuncAttributeMaxDynamicSharedMemorySize,
                         (int)smem_bytes);

    dim3 grid((Nn + NPB - 1) / NPB, Bsz);   // (313, 8)
    fused_attn_kernel<<<grid, THREADS, smem_bytes>>>(
        X, STE_P, STE_Q,
        W21, b21, W22, b22, W23, b23, W24, b24, W25, b25,
        Out);
}